// round 7
// baseline (speedup 1.0000x reference)
#include <cuda_runtime.h>
#include <cuda_bf16.h>
#include <math.h>
#include <stdint.h>

#define BATCH 1024
#define SEQ   512
#define HID   128
#define G3    384

typedef unsigned long long u64;
typedef unsigned short u16;

// h_seq scratch: 1024*512*128 floats = 256MB (static device array: allocation-free)
__device__ float g_hseq[(size_t)BATCH * SEQ * HID];

// ---------------- SMEM layout (bytes) ----------------
// A_lo frags: [12 w][2 t][8 kt][32 lane] uint4 = 98304
// hB_hi: [64 kpair][8 b] u32 (bf16x2)           =  2048
// hB_lo: same                                    =  2048
// Dbuf : [384 row][9] f32                        = 13824
#define OFF_ALO 0
#define OFF_HBH 98304
#define OFF_HBL 100352
#define OFF_D   102400
#define SMEM_BYTES 116224

#define DSTRIDE 9
#define NMMA_WARPS 12
#define NTHREADS 640

__device__ __forceinline__ void mma_bf16(float d[4], const uint4 a, uint32_t b0, uint32_t b1) {
    asm volatile(
        "mma.sync.aligned.m16n8k16.row.col.f32.bf16.bf16.f32 "
        "{%0,%1,%2,%3}, {%4,%5,%6,%7}, {%8,%9}, {%0,%1,%2,%3};"
        : "+f"(d[0]), "+f"(d[1]), "+f"(d[2]), "+f"(d[3])
        : "r"(a.x), "r"(a.y), "r"(a.z), "r"(a.w), "r"(b0), "r"(b1));
}

__device__ __forceinline__ void bsplit(float f, u16& hi, u16& lo) {
    __nv_bfloat16 h = __float2bfloat16(f);
    __nv_bfloat16 l = __float2bfloat16(f - __bfloat162float(h));
    hi = *(u16*)&h;
    lo = *(u16*)&l;
}

__device__ __forceinline__ float fast_sigmoid(float x) {
    float e = __expf(-x);
    return __fdividef(1.0f, 1.0f + e);
}
__device__ __forceinline__ float fast_tanh(float x) {
    float e = __expf(2.0f * x);
    return 1.0f - 2.0f * __fdividef(1.0f, e + 1.0f);
}

// ---------------------------------------------------------------------------
// GRU recurrence, warp-specialized HMMA. 128 CTAs x 640 threads.
// Warps 0-11 (MMA): each owns M-tiles {w, w+12}; A_hi fragments live in
// REGISTERS (64 regs), A_lo fragments in smem, B (h bf16 hi/lo) re-read from
// a 4KB smem buffer. 48 HMMA per warp per step (2 tiles x 8 kt x 3 split
// products), fp32 accum. D written back as scalar STS.32 (alignment-safe).
// Warps 12-19 (gates): 256 threads x 4 (j,b) items: read D from padded smem,
// apply GRU nonlinearity (h_old in registers), write h' bf16 hi/lo splits.
// ---------------------------------------------------------------------------
__global__ __launch_bounds__(NTHREADS, 1) void gru_kernel(
    const float* __restrict__ v_seq,   // [B,S,2]
    const float* __restrict__ W_ih,    // [384,2]
    const float* __restrict__ W_hh,    // [384,128]
    const float* __restrict__ b_ih,    // [384]
    const float* __restrict__ b_hh)    // [384]
{
    extern __shared__ char smem[];
    uint4*    AloFrag = (uint4*)(smem + OFF_ALO);
    uint32_t* hbh     = (uint32_t*)(smem + OFF_HBH);
    uint32_t* hbl     = (uint32_t*)(smem + OFF_HBL);
    u16*      hbh16   = (u16*)(smem + OFF_HBH);
    u16*      hbl16   = (u16*)(smem + OFF_HBL);
    float*    Dbuf    = (float*)(smem + OFF_D);

    const int tid  = threadIdx.x;
    const int wid  = tid >> 5;
    const int lane = tid & 31;
    const int bglob = blockIdx.x * 8;
    const bool is_mma = (wid < NMMA_WARPS);

    // zero h buffers (h0 = 0)
    for (int i = tid; i < 1024; i += NTHREADS) { hbh[i] = 0u; hbl[i] = 0u; }

    // =========================== MMA-warp state ===========================
    uint4 ahi0[8], ahi1[8];          // A_hi fragments, 2 tiles x 8 kt (regs)
    const int bidx0 = (lane & 3) * 8 + (lane >> 2);
    float* dp01[2];
    float* dp23[2];
    const uint4* alo_base = AloFrag + (wid * 16) * 32 + lane;

    if (is_mma) {
        // Build A fragments for tiles T0 = wid, T1 = wid+12
#pragma unroll
        for (int t = 0; t < 2; t++) {
            const int T = wid + t * 12;
            const int r0 = T * 16 + (lane >> 2);
            const int c0 = (lane & 3) * 2;
#pragma unroll
            for (int kt = 0; kt < 8; kt++) {
                const float* p0 = W_hh + r0 * HID + kt * 16 + c0;
                const float* p1 = W_hh + (r0 + 8) * HID + kt * 16 + c0;
                float2 f0 = *(const float2*)(p0);
                float2 f1 = *(const float2*)(p1);
                float2 f2 = *(const float2*)(p0 + 8);
                float2 f3 = *(const float2*)(p1 + 8);
                u16 h0a, l0a, h0b, l0b, h1a, l1a, h1b, l1b;
                u16 h2a, l2a, h2b, l2b, h3a, l3a, h3b, l3b;
                bsplit(f0.x, h0a, l0a); bsplit(f0.y, h0b, l0b);
                bsplit(f1.x, h1a, l1a); bsplit(f1.y, h1b, l1b);
                bsplit(f2.x, h2a, l2a); bsplit(f2.y, h2b, l2b);
                bsplit(f3.x, h3a, l3a); bsplit(f3.y, h3b, l3b);
                uint4 ah, al;
                ah.x = (uint32_t)h0a | ((uint32_t)h0b << 16);
                ah.y = (uint32_t)h1a | ((uint32_t)h1b << 16);
                ah.z = (uint32_t)h2a | ((uint32_t)h2b << 16);
                ah.w = (uint32_t)h3a | ((uint32_t)h3b << 16);
                al.x = (uint32_t)l0a | ((uint32_t)l0b << 16);
                al.y = (uint32_t)l1a | ((uint32_t)l1b << 16);
                al.z = (uint32_t)l2a | ((uint32_t)l2b << 16);
                al.w = (uint32_t)l3a | ((uint32_t)l3b << 16);
                if (t == 0) ahi0[kt] = ah; else ahi1[kt] = ah;
                AloFrag[((wid * 2 + t) * 8 + kt) * 32 + lane] = al;
            }
            dp01[t] = Dbuf + (T * 16 + (lane >> 2)) * DSTRIDE + (lane & 3) * 2;
            dp23[t] = dp01[t] + 8 * DSTRIDE;
        }
    }

    // =========================== gate-warp state ===========================
    const int gt = tid - NMMA_WARPS * 32;      // 0..255 for gate threads
    const int j  = gt & 127;
    const int hf = (gt >> 7) & 1;              // batch half: 0 or 1
    float wr0 = 0, wr1 = 0, wz0 = 0, wz1 = 0, wn0 = 0, wn1 = 0;
    float brt = 0, bzt = 0, bin_ = 0, bhn = 0;
    uint32_t sh_hb = 0;
    if (!is_mma) {
        wr0 = W_ih[2 * j];                wr1 = W_ih[2 * j + 1];
        wz0 = W_ih[2 * (HID + j)];        wz1 = W_ih[2 * (HID + j) + 1];
        wn0 = W_ih[2 * (2 * HID + j)];    wn1 = W_ih[2 * (2 * HID + j) + 1];
        brt = b_ih[j] + b_hh[j];
        bzt = b_ih[HID + j] + b_hh[HID + j];
        bin_ = b_ih[2 * HID + j];
        bhn  = b_hh[2 * HID + j];
        // u16 index base: (j>>1)*16 + (j&1), + b*2 per batch
        sh_hb = (uint32_t)((j >> 1) * 16 + (j & 1));
    }
    float hp[4] = {0.f, 0.f, 0.f, 0.f};

    __syncthreads();

    for (int s = 0; s < SEQ; ++s) {
        if (is_mma) {
            // ---- MMA phase ----
            float acc[2][2][4];
#pragma unroll
            for (int t = 0; t < 2; t++)
#pragma unroll
                for (int p = 0; p < 2; p++)
#pragma unroll
                    for (int e = 0; e < 4; e++) acc[t][p][e] = 0.f;

#pragma unroll
            for (int kt = 0; kt < 8; kt++) {
                const int bi = kt * 64 + bidx0;
                uint32_t bh0 = hbh[bi], bh1 = hbh[bi + 32];
                uint32_t bl0 = hbl[bi], bl1 = hbl[bi + 32];
                uint4 ah0 = ahi0[kt];
                uint4 ah1 = ahi1[kt];
                uint4 al0 = alo_base[kt * 32];
                uint4 al1 = alo_base[(8 + kt) * 32];
                const int p = kt & 1;
                mma_bf16(acc[0][p], ah0, bh0, bh1);
                mma_bf16(acc[1][p], ah1, bh0, bh1);
                mma_bf16(acc[0][p], ah0, bl0, bl1);
                mma_bf16(acc[1][p], ah1, bl0, bl1);
                mma_bf16(acc[0][p], al0, bh0, bh1);
                mma_bf16(acc[1][p], al1, bh0, bh1);
            }
            // scalar stores: DSTRIDE=9 is odd, float2 would misalign on odd rows
#pragma unroll
            for (int t = 0; t < 2; t++) {
                dp01[t][0] = acc[t][0][0] + acc[t][1][0];
                dp01[t][1] = acc[t][0][1] + acc[t][1][1];
                dp23[t][0] = acc[t][0][2] + acc[t][1][2];
                dp23[t][1] = acc[t][0][3] + acc[t][1][3];
            }
            __syncthreads();   // bar1: D ready
            __syncthreads();   // bar2: hB(s) ready (gates ran in between)
        } else {
            // prefetch v for 4 batches (in flight across the MMA phase)
            float2 vv[4];
#pragma unroll
            for (int i = 0; i < 4; i++)
                vv[i] = *(const float2*)(v_seq + ((size_t)(bglob + 4 * hf + i) * SEQ + s) * 2);

            __syncthreads();   // bar1: wait D

            // ---- gate phase: 4 items (j, b=4*hf+i) ----
#pragma unroll
            for (int i = 0; i < 4; i++) {
                const int b = 4 * hf + i;
                float gr = Dbuf[j * DSTRIDE + b];
                float gz = Dbuf[(128 + j) * DSTRIDE + b];
                float gn = Dbuf[(256 + j) * DSTRIDE + b];
                float2 v = vv[i];
                float r = fast_sigmoid(fmaf(wr0, v.x, fmaf(wr1, v.y, brt)) + gr);
                float z = fast_sigmoid(fmaf(wz0, v.x, fmaf(wz1, v.y, bzt)) + gz);
                float n = fast_tanh(fmaf(wn0, v.x, fmaf(wn1, v.y, bin_)) + r * (gn + bhn));
                float hnew = n + z * (hp[i] - n);
                hp[i] = hnew;
                g_hseq[((size_t)(bglob + b) * SEQ + s) * HID + j] = hnew;
                u16 hi, lo;
                bsplit(hnew, hi, lo);
                hbh16[sh_hb + b * 2] = hi;
                hbl16[sh_hb + b * 2] = lo;
            }
            __syncthreads();   // bar2: hB(s) ready
        }
    }
}

// ---------------------------------------------------------------------------
// Epilogue pass 1: x_pred only. One warp per (b,s).
// ---------------------------------------------------------------------------
__global__ __launch_bounds__(256) void epi1_kernel(
    const float* __restrict__ W_out,   // [2,128]
    const float* __restrict__ b_out,   // [2]
    float* __restrict__ out)           // x_pred region: [B*S, 2]
{
    const int w    = (blockIdx.x * blockDim.x + threadIdx.x) >> 5;
    const int lane = threadIdx.x & 31;
    if (w >= BATCH * SEQ) return;

    const float4 w0 = *(const float4*)(W_out + lane * 4);
    const float4 w1 = *(const float4*)(W_out + HID + lane * 4);

    float4 hv = *(const float4*)(g_hseq + (size_t)w * HID + lane * 4);
    float xp0 = hv.x * w0.x + hv.y * w0.y + hv.z * w0.z + hv.w * w0.w;
    float xp1 = hv.x * w1.x + hv.y * w1.y + hv.z * w1.z + hv.w * w1.w;
#pragma unroll
    for (int o = 16; o; o >>= 1) {
        xp0 += __shfl_xor_sync(0xffffffffu, xp0, o);
        xp1 += __shfl_xor_sync(0xffffffffu, xp1, o);
    }
    if (lane == 0) {
        out[2 * (size_t)w]     = xp0 + b_out[0];
        out[2 * (size_t)w + 1] = xp1 + b_out[1];
    }
}

// ---------------------------------------------------------------------------
// Epilogue pass 2: violations. One thread per (b,s).
// ---------------------------------------------------------------------------
__global__ __launch_bounds__(256) void epi2_kernel(
    const float* __restrict__ x0,      // [B,2]
    const float* __restrict__ v_seq,   // [B,S,2]
    const float* __restrict__ W_r1,    // [64,4]
    const float* __restrict__ b_r1,    // [64]
    const float* __restrict__ W_r2,    // [2,64]
    const float* __restrict__ b_r2,    // [2]
    float* __restrict__ out)           // [2, B*S, 2]
{
    __shared__ float4 s_w1[64];
    __shared__ float  s_b1[64], s_w2a[64], s_w2b[64], s_b2[2];
    const int t = threadIdx.x;
    if (t < 64) {
        s_w1[t]  = *(const float4*)(W_r1 + t * 4);
        s_b1[t]  = b_r1[t];
        s_w2a[t] = W_r2[t];
        s_w2b[t] = W_r2[64 + t];
    }
    if (t < 2) s_b2[t] = b_r2[t];
    __syncthreads();

    const int idx = blockIdx.x * blockDim.x + t;
    if (idx >= BATCH * SEQ) return;
    const int b = idx >> 9;
    const int s = idx & 511;

    float xq0, xq1;
    if (s == 0) {
        xq0 = x0[2 * b];
        xq1 = x0[2 * b + 1];
    } else {
        xq0 = out[2 * (size_t)(idx - 1)];
        xq1 = out[2 * (size_t)(idx - 1) + 1];
    }
    const float xp0 = out[2 * (size_t)idx];
    const float xp1 = out[2 * (size_t)idx + 1];
    const float2 vv = *(const float2*)(v_seq + (size_t)idx * 2);

    float r0 = 0.0f, r1 = 0.0f;
#pragma unroll 8
    for (int m = 0; m < 64; m++) {
        float4 wq = s_w1[m];
        float h = fmaf(wq.x, xq0, fmaf(wq.y, xq1, fmaf(wq.z, vv.x, fmaf(wq.w, vv.y, s_b1[m]))));
        h = fmaxf(h, 0.0f);
        r0 = fmaf(h, s_w2a[m], r0);
        r1 = fmaf(h, s_w2b[m], r1);
    }
    const float pp0 = xq0 + vv.x + r0 + s_b2[0];
    const float pp1 = xq1 + vv.y + r1 + s_b2[1];

    const size_t off = (size_t)BATCH * SEQ * 2;
    out[off + 2 * (size_t)idx]     = xp0 - pp0;
    out[off + 2 * (size_t)idx + 1] = xp1 - pp1;
}

// ---------------------------------------------------------------------------
extern "C" void kernel_launch(void* const* d_in, const int* in_sizes, int n_in,
                              void* d_out, int out_size)
{
    const float* x0    = (const float*)d_in[0];
    const float* v_seq = (const float*)d_in[1];
    const float* W_ih  = (const float*)d_in[2];
    const float* W_hh  = (const float*)d_in[3];
    const float* b_ih  = (const float*)d_in[4];
    const float* b_hh  = (const float*)d_in[5];
    const float* W_out = (const float*)d_in[6];
    const float* b_out = (const float*)d_in[7];
    const float* W_r1  = (const float*)d_in[8];
    const float* b_r1  = (const float*)d_in[9];
    const float* W_r2  = (const float*)d_in[10];
    const float* b_r2  = (const float*)d_in[11];
    float* out = (float*)d_out;

    cudaFuncSetAttribute(gru_kernel, cudaFuncAttributeMaxDynamicSharedMemorySize, SMEM_BYTES);
    gru_kernel<<<BATCH / 8, NTHREADS, SMEM_BYTES>>>(v_seq, W_ih, W_hh, b_ih, b_hh);

    // pass 1: x_pred (one warp per (b,s))
    {
        const int total = BATCH * SEQ * 32;
        epi1_kernel<<<(total + 255) / 256, 256>>>(W_out, b_out, out);
    }
    // pass 2: violations (one thread per (b,s))
    {
        const int total = BATCH * SEQ;
        epi2_kernel<<<(total + 255) / 256, 256>>>(x0, v_seq, W_r1, b_r1, W_r2, b_r2, out);
    }
}

// round 8
// speedup vs baseline: 1.5333x; 1.5333x over previous
#include <cuda_runtime.h>
#include <cuda_bf16.h>
#include <math.h>
#include <stdint.h>

#define BATCH 1024
#define SEQ   512
#define HID   128
#define G3    384

typedef unsigned long long u64;
typedef unsigned short u16;

// h_seq scratch: 1024*512*128 floats = 256MB (static device array: allocation-free)
__device__ float g_hseq[(size_t)BATCH * SEQ * HID];

// ---------------- SMEM layout (bytes) ----------------
// A_lo frags: [24 tile][8 kt][32 lane] uint4 = 98304
// hB_hi: [64 kpair][8 b] u32 (bf16x2)         =  2048
// hB_lo: same                                  =  2048
// Dbuf : [384 row][10] f32                     = 15360
#define OFF_ALO 0
#define OFF_HBH 98304
#define OFF_HBL 100352
#define OFF_D   102400
#define SMEM_BYTES 117760

#define DSTRIDE 10
#define NTHREADS 768

__device__ __forceinline__ void mma_bf16(float d[4], const uint4 a, uint32_t b0, uint32_t b1) {
    asm volatile(
        "mma.sync.aligned.m16n8k16.row.col.f32.bf16.bf16.f32 "
        "{%0,%1,%2,%3}, {%4,%5,%6,%7}, {%8,%9}, {%0,%1,%2,%3};"
        : "+f"(d[0]), "+f"(d[1]), "+f"(d[2]), "+f"(d[3])
        : "r"(a.x), "r"(a.y), "r"(a.z), "r"(a.w), "r"(b0), "r"(b1));
}

__device__ __forceinline__ void bsplit(float f, u16& hi, u16& lo) {
    __nv_bfloat16 h = __float2bfloat16(f);
    __nv_bfloat16 l = __float2bfloat16(f - __bfloat162float(h));
    hi = *(u16*)&h;
    lo = *(u16*)&l;
}

__device__ __forceinline__ float fast_sigmoid(float x) {
    float e = __expf(-x);
    return __fdividef(1.0f, 1.0f + e);
}
__device__ __forceinline__ float fast_tanh(float x) {
    float e = __expf(2.0f * x);
    return 1.0f - 2.0f * __fdividef(1.0f, e + 1.0f);
}

// ---------------------------------------------------------------------------
// GRU recurrence via bf16-split HMMA. 128 CTAs x 768 threads (24 warps),
// 8 batches per CTA. Every warp owns ONE M-tile (16 rows of the 384-row gate
// matrix): A_hi fragments in REGISTERS (32 regs), A_lo fragments in smem.
// Per step: 24 HMMA/warp (8 kt x {hi*hi, hi*lo, lo*hi}), fp32 accum, D to
// padded smem (float2, stride 10 = aligned); then threads 0-511 apply the
// gate nonlinearity for 2 (j,b) items each and write h' bf16 hi/lo splits.
// ---------------------------------------------------------------------------
__global__ __launch_bounds__(NTHREADS, 1) void gru_kernel(
    const float* __restrict__ v_seq,   // [B,S,2]
    const float* __restrict__ W_ih,    // [384,2]
    const float* __restrict__ W_hh,    // [384,128]
    const float* __restrict__ b_ih,    // [384]
    const float* __restrict__ b_hh)    // [384]
{
    extern __shared__ char smem[];
    uint4*    AloFrag = (uint4*)(smem + OFF_ALO);
    uint32_t* hbh     = (uint32_t*)(smem + OFF_HBH);
    uint32_t* hbl     = (uint32_t*)(smem + OFF_HBL);
    u16*      hbh16   = (u16*)(smem + OFF_HBH);
    u16*      hbl16   = (u16*)(smem + OFF_HBL);
    float*    Dbuf    = (float*)(smem + OFF_D);

    const int tid  = threadIdx.x;
    const int wid  = tid >> 5;
    const int lane = tid & 31;
    const int bglob = blockIdx.x * 8;

    // zero h buffers (h0 = 0)
    for (int i = tid; i < 1024; i += NTHREADS) { hbh[i] = 0u; hbl[i] = 0u; }

    // ---- Build A fragments for tile T = wid: hi -> regs, lo -> smem ----
    uint4 ahi[8];
    {
        const int r0 = wid * 16 + (lane >> 2);
        const int c0 = (lane & 3) * 2;
#pragma unroll
        for (int kt = 0; kt < 8; kt++) {
            const float* p0 = W_hh + r0 * HID + kt * 16 + c0;
            const float* p1 = W_hh + (r0 + 8) * HID + kt * 16 + c0;
            float2 f0 = *(const float2*)(p0);
            float2 f1 = *(const float2*)(p1);
            float2 f2 = *(const float2*)(p0 + 8);
            float2 f3 = *(const float2*)(p1 + 8);
            u16 h0a, l0a, h0b, l0b, h1a, l1a, h1b, l1b;
            u16 h2a, l2a, h2b, l2b, h3a, l3a, h3b, l3b;
            bsplit(f0.x, h0a, l0a); bsplit(f0.y, h0b, l0b);
            bsplit(f1.x, h1a, l1a); bsplit(f1.y, h1b, l1b);
            bsplit(f2.x, h2a, l2a); bsplit(f2.y, h2b, l2b);
            bsplit(f3.x, h3a, l3a); bsplit(f3.y, h3b, l3b);
            uint4 ah, al;
            ah.x = (uint32_t)h0a | ((uint32_t)h0b << 16);
            ah.y = (uint32_t)h1a | ((uint32_t)h1b << 16);
            ah.z = (uint32_t)h2a | ((uint32_t)h2b << 16);
            ah.w = (uint32_t)h3a | ((uint32_t)h3b << 16);
            al.x = (uint32_t)l0a | ((uint32_t)l0b << 16);
            al.y = (uint32_t)l1a | ((uint32_t)l1b << 16);
            al.z = (uint32_t)l2a | ((uint32_t)l2b << 16);
            al.w = (uint32_t)l3a | ((uint32_t)l3b << 16);
            ahi[kt] = ah;
            AloFrag[(wid * 8 + kt) * 32 + lane] = al;
        }
    }
    const uint4* alo_base = AloFrag + (wid * 8) * 32 + lane;
    const int bidx0 = (lane & 3) * 8 + (lane >> 2);
    float* dp01 = Dbuf + (wid * 16 + (lane >> 2)) * DSTRIDE + (lane & 3) * 2;
    float* dp23 = dp01 + 8 * DSTRIDE;

    // ---- Gate constants (threads 0..511: thread owns (j, batches bp, bp+4)) ----
    const int j  = tid & 127;
    const int bp = (tid >> 7) & 3;
    const bool is_gate = (tid < 512);
    float wr0 = 0, wr1 = 0, wz0 = 0, wz1 = 0, wn0 = 0, wn1 = 0;
    float brt = 0, bzt = 0, bin_ = 0, bhn = 0;
    if (is_gate) {
        wr0 = W_ih[2 * j];                wr1 = W_ih[2 * j + 1];
        wz0 = W_ih[2 * (HID + j)];        wz1 = W_ih[2 * (HID + j) + 1];
        wn0 = W_ih[2 * (2 * HID + j)];    wn1 = W_ih[2 * (2 * HID + j) + 1];
        brt = b_ih[j] + b_hh[j];
        bzt = b_ih[HID + j] + b_hh[HID + j];
        bin_ = b_ih[2 * HID + j];
        bhn  = b_hh[2 * HID + j];
    }
    // u16 index base in hB: (j>>1)*16 + (j&1), + b*2 per batch
    const uint32_t sh_hb = (uint32_t)((j >> 1) * 16 + (j & 1));
    float hp[2] = {0.f, 0.f};

    __syncthreads();

    for (int s = 0; s < SEQ; ++s) {
        // prefetch v (gate threads) — in flight across the MMA phase
        float2 vv[2];
        if (is_gate) {
            vv[0] = *(const float2*)(v_seq + ((size_t)(bglob + bp) * SEQ + s) * 2);
            vv[1] = *(const float2*)(v_seq + ((size_t)(bglob + bp + 4) * SEQ + s) * 2);
        }

        // ---- MMA phase: all 24 warps, 1 tile each ----
        float d0[4] = {0.f, 0.f, 0.f, 0.f};
        float d1[4] = {0.f, 0.f, 0.f, 0.f};
#pragma unroll
        for (int kt = 0; kt < 8; kt++) {
            const int bi = kt * 64 + bidx0;
            uint32_t bh0 = hbh[bi], bh1 = hbh[bi + 32];
            uint32_t bl0 = hbl[bi], bl1 = hbl[bi + 32];
            uint4 ah = ahi[kt];
            uint4 al = alo_base[kt * 32];
            float* dd = (kt & 1) ? d1 : d0;
            mma_bf16(dd, ah, bh0, bh1);
            mma_bf16(dd, ah, bl0, bl1);
            mma_bf16(dd, al, bh0, bh1);
        }
        *(float2*)(dp01) = make_float2(d0[0] + d1[0], d0[1] + d1[1]);
        *(float2*)(dp23) = make_float2(d0[2] + d1[2], d0[3] + d1[3]);
        __syncthreads();   // bar1: D ready

        // ---- Gate phase: threads 0..511 ----
        if (is_gate) {
#pragma unroll
            for (int i = 0; i < 2; i++) {
                const int b = bp + 4 * i;
                float gr = Dbuf[j * DSTRIDE + b];
                float gz = Dbuf[(128 + j) * DSTRIDE + b];
                float gn = Dbuf[(256 + j) * DSTRIDE + b];
                float2 v = vv[i];
                float r = fast_sigmoid(fmaf(wr0, v.x, fmaf(wr1, v.y, brt)) + gr);
                float z = fast_sigmoid(fmaf(wz0, v.x, fmaf(wz1, v.y, bzt)) + gz);
                float n = fast_tanh(fmaf(wn0, v.x, fmaf(wn1, v.y, bin_)) + r * (gn + bhn));
                float hnew = n + z * (hp[i] - n);
                hp[i] = hnew;
                g_hseq[((size_t)(bglob + b) * SEQ + s) * HID + j] = hnew;
                u16 hi, lo;
                bsplit(hnew, hi, lo);
                hbh16[sh_hb + b * 2] = hi;
                hbl16[sh_hb + b * 2] = lo;
            }
        }
        __syncthreads();   // bar2: hB(s) ready
    }
}

// ---------------------------------------------------------------------------
// Epilogue pass 1: x_pred only. One warp per (b,s).
// ---------------------------------------------------------------------------
__global__ __launch_bounds__(256) void epi1_kernel(
    const float* __restrict__ W_out,   // [2,128]
    const float* __restrict__ b_out,   // [2]
    float* __restrict__ out)           // x_pred region: [B*S, 2]
{
    const int w    = (blockIdx.x * blockDim.x + threadIdx.x) >> 5;
    const int lane = threadIdx.x & 31;
    if (w >= BATCH * SEQ) return;

    const float4 w0 = *(const float4*)(W_out + lane * 4);
    const float4 w1 = *(const float4*)(W_out + HID + lane * 4);

    float4 hv = *(const float4*)(g_hseq + (size_t)w * HID + lane * 4);
    float xp0 = hv.x * w0.x + hv.y * w0.y + hv.z * w0.z + hv.w * w0.w;
    float xp1 = hv.x * w1.x + hv.y * w1.y + hv.z * w1.z + hv.w * w1.w;
#pragma unroll
    for (int o = 16; o; o >>= 1) {
        xp0 += __shfl_xor_sync(0xffffffffu, xp0, o);
        xp1 += __shfl_xor_sync(0xffffffffu, xp1, o);
    }
    if (lane == 0) {
        out[2 * (size_t)w]     = xp0 + b_out[0];
        out[2 * (size_t)w + 1] = xp1 + b_out[1];
    }
}

// ---------------------------------------------------------------------------
// Epilogue pass 2: violations. One thread per (b,s).
// ---------------------------------------------------------------------------
__global__ __launch_bounds__(256) void epi2_kernel(
    const float* __restrict__ x0,      // [B,2]
    const float* __restrict__ v_seq,   // [B,S,2]
    const float* __restrict__ W_r1,    // [64,4]
    const float* __restrict__ b_r1,    // [64]
    const float* __restrict__ W_r2,    // [2,64]
    const float* __restrict__ b_r2,    // [2]
    float* __restrict__ out)           // [2, B*S, 2]
{
    __shared__ float4 s_w1[64];
    __shared__ float  s_b1[64], s_w2a[64], s_w2b[64], s_b2[2];
    const int t = threadIdx.x;
    if (t < 64) {
        s_w1[t]  = *(const float4*)(W_r1 + t * 4);
        s_b1[t]  = b_r1[t];
        s_w2a[t] = W_r2[t];
        s_w2b[t] = W_r2[64 + t];
    }
    if (t < 2) s_b2[t] = b_r2[t];
    __syncthreads();

    const int idx = blockIdx.x * blockDim.x + t;
    if (idx >= BATCH * SEQ) return;
    const int b = idx >> 9;
    const int s = idx & 511;

    float xq0, xq1;
    if (s == 0) {
        xq0 = x0[2 * b];
        xq1 = x0[2 * b + 1];
    } else {
        xq0 = out[2 * (size_t)(idx - 1)];
        xq1 = out[2 * (size_t)(idx - 1) + 1];
    }
    const float xp0 = out[2 * (size_t)idx];
    const float xp1 = out[2 * (size_t)idx + 1];
    const float2 vv = *(const float2*)(v_seq + (size_t)idx * 2);

    float r0 = 0.0f, r1 = 0.0f;
#pragma unroll 8
    for (int m = 0; m < 64; m++) {
        float4 wq = s_w1[m];
        float h = fmaf(wq.x, xq0, fmaf(wq.y, xq1, fmaf(wq.z, vv.x, fmaf(wq.w, vv.y, s_b1[m]))));
        h = fmaxf(h, 0.0f);
        r0 = fmaf(h, s_w2a[m], r0);
        r1 = fmaf(h, s_w2b[m], r1);
    }
    const float pp0 = xq0 + vv.x + r0 + s_b2[0];
    const float pp1 = xq1 + vv.y + r1 + s_b2[1];

    const size_t off = (size_t)BATCH * SEQ * 2;
    out[off + 2 * (size_t)idx]     = xp0 - pp0;
    out[off + 2 * (size_t)idx + 1] = xp1 - pp1;
}

// ---------------------------------------------------------------------------
extern "C" void kernel_launch(void* const* d_in, const int* in_sizes, int n_in,
                              void* d_out, int out_size)
{
    const float* x0    = (const float*)d_in[0];
    const float* v_seq = (const float*)d_in[1];
    const float* W_ih  = (const float*)d_in[2];
    const float* W_hh  = (const float*)d_in[3];
    const float* b_ih  = (const float*)d_in[4];
    const float* b_hh  = (const float*)d_in[5];
    const float* W_out = (const float*)d_in[6];
    const float* b_out = (const float*)d_in[7];
    const float* W_r1  = (const float*)d_in[8];
    const float* b_r1  = (const float*)d_in[9];
    const float* W_r2  = (const float*)d_in[10];
    const float* b_r2  = (const float*)d_in[11];
    float* out = (float*)d_out;

    cudaFuncSetAttribute(gru_kernel, cudaFuncAttributeMaxDynamicSharedMemorySize, SMEM_BYTES);
    gru_kernel<<<BATCH / 8, NTHREADS, SMEM_BYTES>>>(v_seq, W_ih, W_hh, b_ih, b_hh);

    // pass 1: x_pred (one warp per (b,s))
    {
        const int total = BATCH * SEQ * 32;
        epi1_kernel<<<(total + 255) / 256, 256>>>(W_out, b_out, out);
    }
    // pass 2: violations (one thread per (b,s))
    {
        const int total = BATCH * SEQ;
        epi2_kernel<<<(total + 255) / 256, 256>>>(x0, v_seq, W_r1, b_r1, W_r2, b_r2, out);
    }
}